// round 1
// baseline (speedup 1.0000x reference)
#include <cuda_runtime.h>
#include <math.h>

#define NE   16
#define TILE 128
#define BK   16
#define EPAD 16

// ---------------- scratch (device globals; no allocation allowed) -----------
__device__ float g_nemb[4096 * 1024];   // normalized embeddings
__device__ float g_logp[4096 * NE];     // log_softmax(routing_probs)
__device__ float g_q[4096 * NE];        // softmax(routing_probs)
__device__ float g_negent[4096];        // sum q*logq per row
__device__ float g_cons;                // consistency numerator accumulator
__device__ unsigned long long g_pairs;  // ordered masked-pair count

// ---------------------------------------------------------------------------
__global__ void zero_kernel() {
    g_cons  = 0.f;
    g_pairs = 0ull;
}

// One warp per row: softmax stats for routing_probs + embedding normalization.
__global__ void prep_kernel(const float* __restrict__ rp,
                            const float* __restrict__ emb,
                            int B, int H) {
    int warp_id = (blockIdx.x * blockDim.x + threadIdx.x) >> 5;
    int lane    = threadIdx.x & 31;
    if (warp_id >= B) return;

    // --- softmax over the 16 routing probs (lanes 0..15 hold data) ---
    const float* prow = rp + (size_t)warp_id * NE;
    float p  = (lane < NE) ? prow[lane] : 0.f;
    float pm = (lane < NE) ? p : -1e30f;
    #pragma unroll
    for (int o = 16; o; o >>= 1) pm = fmaxf(pm, __shfl_xor_sync(0xffffffffu, pm, o));
    float ex = (lane < NE) ? expf(p - pm) : 0.f;
    float s  = ex;
    #pragma unroll
    for (int o = 16; o; o >>= 1) s += __shfl_xor_sync(0xffffffffu, s, o);
    float lse = logf(s);
    float lp  = p - pm - lse;
    float qv  = expf(lp);
    float ne  = (lane < NE) ? qv * lp : 0.f;
    #pragma unroll
    for (int o = 16; o; o >>= 1) ne += __shfl_xor_sync(0xffffffffu, ne, o);
    if (lane < NE) {
        g_logp[warp_id * NE + lane] = lp;
        g_q[warp_id * NE + lane]    = qv;
    }
    if (lane == 0) g_negent[warp_id] = ne;

    // --- normalize embedding row ---
    const float* erow = emb + (size_t)warp_id * H;
    float ss = 0.f;
    for (int c = lane; c < H; c += 32) { float v = erow[c]; ss += v * v; }
    #pragma unroll
    for (int o = 16; o; o >>= 1) ss += __shfl_xor_sync(0xffffffffu, ss, o);
    float inv = 1.f / sqrtf(ss);
    float* nrow = g_nemb + (size_t)warp_id * H;
    for (int c = lane; c < H; c += 32) nrow[c] = erow[c] * inv;
}

// ---------------------------------------------------------------------------
// Upper-triangular tile GEMM (sim = nemb @ nemb^T) fused with mask + KL.
// 128x128 tile per block, 256 threads, 8x8 per thread, BK=16.
__global__ void __launch_bounds__(256, 2)
pairs_kernel(int B, int H) {
    __shared__ float sm[4 * TILE * EPAD + 2 * TILE];  // 8448 floats (33.8 KB)
    float* As = sm;               // [BK][TILE] during mainloop
    float* Bs = sm + BK * TILE;

    int nT = B / TILE;
    int t  = blockIdx.x;
    int I = 0, rem = t;
    while (rem >= nT - I) { rem -= nT - I; I++; }
    int J = I + rem;              // I <= J

    int tid = threadIdx.x;
    int tx = tid & 15, ty = tid >> 4;

    float acc[8][8];
    #pragma unroll
    for (int r = 0; r < 8; r++)
        #pragma unroll
        for (int c = 0; c < 8; c++) acc[r][c] = 0.f;

    const float* Ag = g_nemb + (size_t)(I * TILE) * H;
    const float* Bg = g_nemb + (size_t)(J * TILE) * H;

    for (int kb = 0; kb < H; kb += BK) {
        // cooperative load: 128x16 of A and B, transposed into [k][row]
        #pragma unroll
        for (int pass = 0; pass < 2; pass++) {
            int linear = tid + pass * 256;           // 0..511
            int row = linear >> 2;
            int f4  = linear & 3;
            float4 va = *(const float4*)(Ag + (size_t)row * H + kb + f4 * 4);
            As[(f4 * 4 + 0) * TILE + row] = va.x;
            As[(f4 * 4 + 1) * TILE + row] = va.y;
            As[(f4 * 4 + 2) * TILE + row] = va.z;
            As[(f4 * 4 + 3) * TILE + row] = va.w;
            float4 vb = *(const float4*)(Bg + (size_t)row * H + kb + f4 * 4);
            Bs[(f4 * 4 + 0) * TILE + row] = vb.x;
            Bs[(f4 * 4 + 1) * TILE + row] = vb.y;
            Bs[(f4 * 4 + 2) * TILE + row] = vb.z;
            Bs[(f4 * 4 + 3) * TILE + row] = vb.w;
        }
        __syncthreads();
        #pragma unroll
        for (int k = 0; k < BK; k++) {
            float a[8], b[8];
            float4 a0 = *(float4*)&As[k * TILE + ty * 8];
            float4 a1 = *(float4*)&As[k * TILE + ty * 8 + 4];
            float4 b0 = *(float4*)&Bs[k * TILE + tx * 8];
            float4 b1 = *(float4*)&Bs[k * TILE + tx * 8 + 4];
            a[0]=a0.x; a[1]=a0.y; a[2]=a0.z; a[3]=a0.w;
            a[4]=a1.x; a[5]=a1.y; a[6]=a1.z; a[7]=a1.w;
            b[0]=b0.x; b[1]=b0.y; b[2]=b0.z; b[3]=b0.w;
            b[4]=b1.x; b[5]=b1.y; b[6]=b1.z; b[7]=b1.w;
            #pragma unroll
            for (int r = 0; r < 8; r++)
                #pragma unroll
                for (int c = 0; c < 8; c++)
                    acc[r][c] += a[r] * b[c];
        }
        __syncthreads();
    }

    // ---- epilogue: reload smem with logp/q/negent for tile rows & cols ----
    float* lpI = sm;
    float* qI  = sm + 1 * TILE * EPAD;
    float* lpJ = sm + 2 * TILE * EPAD;
    float* qJ  = sm + 3 * TILE * EPAD;
    float* neI = sm + 4 * TILE * EPAD;
    float* neJ = neI + TILE;

    for (int idx = tid; idx < TILE * NE; idx += 256) {
        int row = idx >> 4;
        int e   = idx & 15;
        lpI[row * EPAD + e] = g_logp[(size_t)(I * TILE + row) * NE + e];
        qI [row * EPAD + e] = g_q   [(size_t)(I * TILE + row) * NE + e];
        lpJ[row * EPAD + e] = g_logp[(size_t)(J * TILE + row) * NE + e];
        qJ [row * EPAD + e] = g_q   [(size_t)(J * TILE + row) * NE + e];
    }
    if (tid < TILE) {
        neI[tid] = g_negent[I * TILE + tid];
        neJ[tid] = g_negent[J * TILE + tid];
    }
    __syncthreads();

    int ri0 = ty * 8, cj0 = tx * 8;
    unsigned long long mask = 0ull;
    int   cnt    = 0;
    float negsum = 0.f;
    #pragma unroll
    for (int r = 0; r < 8; r++) {
        #pragma unroll
        for (int c = 0; c < 8; c++) {
            bool on = (acc[r][c] > 0.f) && (I != J || (ri0 + r) < (cj0 + c));
            if (on) {
                mask |= 1ull << (r * 8 + c);
                cnt  += 2;                     // ordered pairs (i,j) and (j,i)
                negsum += neI[ri0 + r] + neJ[cj0 + c];
            }
        }
    }

    float dsum = 0.f;
    #pragma unroll 1
    for (int e = 0; e < NE; e++) {
        float lpi[8], qi[8], lpj[8], qj[8];
        #pragma unroll
        for (int r = 0; r < 8; r++) {
            lpi[r] = lpI[(ri0 + r) * EPAD + e];
            qi[r]  = qI [(ri0 + r) * EPAD + e];
        }
        #pragma unroll
        for (int c = 0; c < 8; c++) {
            lpj[c] = lpJ[(cj0 + c) * EPAD + e];
            qj[c]  = qJ [(cj0 + c) * EPAD + e];
        }
        #pragma unroll
        for (int r = 0; r < 8; r++)
            #pragma unroll
            for (int c = 0; c < 8; c++)
                if ((mask >> (r * 8 + c)) & 1ull)
                    dsum += lpi[r] * qj[c] + lpj[c] * qi[r];
    }
    float consl = negsum - dsum;

    // block reduce + atomics
    #pragma unroll
    for (int o = 16; o; o >>= 1) {
        consl += __shfl_xor_sync(0xffffffffu, consl, o);
        cnt   += __shfl_xor_sync(0xffffffffu, cnt, o);
    }
    __shared__ float wsum[8];
    __shared__ int   wcnt[8];
    int wid = tid >> 5;
    if ((tid & 31) == 0) { wsum[wid] = consl; wcnt[wid] = cnt; }
    __syncthreads();
    if (tid == 0) {
        float cs = 0.f; int cc = 0;
        #pragma unroll
        for (int w = 0; w < 8; w++) { cs += wsum[w]; cc += wcnt[w]; }
        atomicAdd(&g_cons, cs);
        atomicAdd(&g_pairs, (unsigned long long)cc);
    }
}

// ---------------------------------------------------------------------------
__global__ void finalize_kernel(const float* __restrict__ rp, int B,
                                float* __restrict__ out) {
    int tid = threadIdx.x;
    float us = 0.f, ent = 0.f, eff = 0.f;
    int total = B * NE;
    // stride 256 is a multiple of 16 -> each thread's elements share expert tid&15
    for (int idx = tid; idx < total; idx += 256) {
        float p = rp[idx];
        us += p;
        ent += p * logf(p + 1e-8f);
        if (p < 0.1f) eff += p;
    }
    __shared__ float s_us[256];
    __shared__ float s_ent[256];
    __shared__ float s_eff[256];
    s_us[tid] = us; s_ent[tid] = ent; s_eff[tid] = eff;
    __syncthreads();
    if (tid == 0) {
        float usage[NE];
        #pragma unroll
        for (int e = 0; e < NE; e++) usage[e] = 0.f;
        float es = 0.f, fs = 0.f;
        for (int i = 0; i < 256; i++) {
            usage[i & 15] += s_us[i];
            es += s_ent[i];
            fs += s_eff[i];
        }
        float invB = 1.f / (float)B;
        float mean = 0.f;
        #pragma unroll
        for (int e = 0; e < NE; e++) { usage[e] *= invB; mean += usage[e]; }
        mean /= (float)NE;
        float var = 0.f;
        #pragma unroll
        for (int e = 0; e < NE; e++) { float d = usage[e] - mean; var += d * d; }
        var /= (float)(NE - 1);
        float load_balance = var * (float)(NE * NE);
        float entropy_loss = es * invB;   // = mean(sum p*log(p+eps))
        float efficiency   = fs * invB;
        unsigned long long np = g_pairs;
        float cons = (np > 0) ? (g_cons / (float)np) : 0.f;
        out[0] = load_balance + entropy_loss + efficiency + cons;
    }
}

// ---------------------------------------------------------------------------
extern "C" void kernel_launch(void* const* d_in, const int* in_sizes, int n_in,
                              void* d_out, int out_size) {
    const float* rp  = (const float*)d_in[0];
    const float* emb = (const float*)d_in[1];
    float* out = (float*)d_out;
    int B = in_sizes[0] / NE;     // 4096
    int H = in_sizes[1] / B;      // 1024

    zero_kernel<<<1, 1>>>();
    prep_kernel<<<(B * 32 + 255) / 256, 256>>>(rp, emb, B, H);
    int nT = B / TILE;
    int ntiles = nT * (nT + 1) / 2;   // upper-triangular tiles: 528
    pairs_kernel<<<ntiles, 256>>>(B, H);
    finalize_kernel<<<1, 256>>>(rp, B, out);
}

// round 5
// speedup vs baseline: 5.8704x; 5.8704x over previous
#include <cuda_runtime.h>
#include <cuda_bf16.h>
#include <math.h>
#include <stdint.h>

#define NE    16
#define TILE  128
#define KC    128            // bf16 K-columns per chunk
#define BDIM  256
#define HDIM  1024
#define BROWS 4096

// ---- smem layout (bytes): AB double-buffer | pq tiles | ne vectors --------
#define PQ_OFF     131072                    // 8 tiles x 4096B (128 x 16 bf16)
#define NEI_OFF    (PQ_OFF + 8 * 4096)       // 163840
#define NEJ_OFF    (NEI_OFF + 512)
#define SMEM_BYTES (NEJ_OFF + 512)           // 164864

// pq tile order: 0 lpI_hi, 1 lpI_lo, 2 qI_hi, 3 qI_lo, 4 lpJ_hi, 5 lpJ_lo, 6 qJ_hi, 7 qJ_lo

// ---- device scratch --------------------------------------------------------
__device__ __align__(16) __nv_bfloat16 g_nembh[BROWS * HDIM];
__device__ __align__(16) __nv_bfloat16 g_pq[BROWS * 64];  // lp_hi|lp_lo|q_hi|q_lo per row
__device__ float g_negent[BROWS];
__device__ float g_cons, g_ent, g_eff;
__device__ float g_usage[NE];
__device__ unsigned long long g_pairs;

// ---- helpers ---------------------------------------------------------------
__device__ __forceinline__ uint32_t smem_u32(const void* p) {
    uint32_t a;
    asm("{ .reg .u64 t; cvta.to.shared.u64 t, %1; cvt.u32.u64 %0, t; }" : "=r"(a) : "l"(p));
    return a;
}
__device__ __forceinline__ void ldsm4(uint32_t (&r)[4], uint32_t addr) {
    asm volatile("ldmatrix.sync.aligned.m8n8.x4.shared.b16 {%0,%1,%2,%3}, [%4];"
                 : "=r"(r[0]), "=r"(r[1]), "=r"(r[2]), "=r"(r[3]) : "r"(addr));
}
__device__ __forceinline__ void mma16816(float (&d)[4], const uint32_t (&a)[4],
                                         uint32_t b0, uint32_t b1) {
    asm volatile("mma.sync.aligned.m16n8k16.row.col.f32.bf16.bf16.f32 "
        "{%0,%1,%2,%3}, {%4,%5,%6,%7}, {%8,%9}, {%0,%1,%2,%3};"
        : "+f"(d[0]), "+f"(d[1]), "+f"(d[2]), "+f"(d[3])
        : "r"(a[0]), "r"(a[1]), "r"(a[2]), "r"(a[3]), "r"(b0), "r"(b1));
}
#define CP_ASYNC16(sa, ga) \
    asm volatile("cp.async.cg.shared.global [%0], [%1], 16;" :: "r"(sa), "l"(ga) : "memory")
#define CP_COMMIT()  asm volatile("cp.async.commit_group;" ::: "memory")
#define CP_WAIT1()   asm volatile("cp.async.wait_group 1;" ::: "memory")
#define CP_WAIT0()   asm volatile("cp.async.wait_group 0;" ::: "memory")

// ---------------------------------------------------------------------------
__global__ void zero_kernel() {
    g_cons = 0.f; g_ent = 0.f; g_eff = 0.f; g_pairs = 0ull;
    #pragma unroll
    for (int e = 0; e < NE; e++) g_usage[e] = 0.f;
}

// One warp per row: softmax stats, hi/lo bf16 splits, normalized bf16
// embeddings, plus block-reduced usage/entropy/efficiency partials.
__global__ void __launch_bounds__(BDIM)
prep_kernel(const float* __restrict__ rp, const float* __restrict__ emb,
            int B, int H) {
    __shared__ float s_usage[NE];
    __shared__ float s_ent, s_eff;
    int tid = threadIdx.x;
    if (tid < NE) s_usage[tid] = 0.f;
    if (tid == 0) { s_ent = 0.f; s_eff = 0.f; }
    __syncthreads();

    int lane = tid & 31;
    int row  = blockIdx.x * (BDIM / 32) + (tid >> 5);

    const float* prow = rp + (size_t)row * NE;
    float p  = (lane < NE) ? prow[lane] : 0.f;
    float pm = (lane < NE) ? p : -1e30f;
    #pragma unroll
    for (int o = 8; o; o >>= 1) pm = fmaxf(pm, __shfl_xor_sync(0xffffffffu, pm, o));
    float ex = (lane < NE) ? expf(p - pm) : 0.f;
    float s  = ex;
    #pragma unroll
    for (int o = 8; o; o >>= 1) s += __shfl_xor_sync(0xffffffffu, s, o);
    float lse = logf(s);
    float lp  = p - pm - lse;
    float qv  = expf(lp);
    float ne   = (lane < NE) ? qv * lp : 0.f;
    float entp = (lane < NE) ? p * logf(p + 1e-8f) : 0.f;
    float effp = (lane < NE && p < 0.1f) ? p : 0.f;
    #pragma unroll
    for (int o = 8; o; o >>= 1) {
        ne   += __shfl_xor_sync(0xffffffffu, ne, o);
        entp += __shfl_xor_sync(0xffffffffu, entp, o);
        effp += __shfl_xor_sync(0xffffffffu, effp, o);
    }
    if (lane < NE) {
        __nv_bfloat16 lph = __float2bfloat16(lp);
        __nv_bfloat16 lpl = __float2bfloat16(lp - __bfloat162float(lph));
        __nv_bfloat16 qh  = __float2bfloat16(qv);
        __nv_bfloat16 ql  = __float2bfloat16(qv - __bfloat162float(qh));
        size_t b = (size_t)row * 64;
        g_pq[b + lane]      = lph;
        g_pq[b + 16 + lane] = lpl;
        g_pq[b + 32 + lane] = qh;
        g_pq[b + 48 + lane] = ql;
        atomicAdd(&s_usage[lane], p);
    }
    if (lane == 0) {
        g_negent[row] = ne;
        atomicAdd(&s_ent, entp);
        atomicAdd(&s_eff, effp);
    }

    const float* erow = emb + (size_t)row * H;
    float ss = 0.f;
    for (int c = lane; c < H; c += 32) { float v = erow[c]; ss += v * v; }
    #pragma unroll
    for (int o = 16; o; o >>= 1) ss += __shfl_xor_sync(0xffffffffu, ss, o);
    float inv = 1.f / sqrtf(ss);
    __nv_bfloat16* nrow = g_nembh + (size_t)row * H;
    for (int c = lane; c < H; c += 32) nrow[c] = __float2bfloat16(erow[c] * inv);

    __syncthreads();
    if (tid < NE) atomicAdd(&g_usage[tid], s_usage[tid]);
    if (tid == 0) { atomicAdd(&g_ent, s_ent); atomicAdd(&g_eff, s_eff); }
}

// ---------------------------------------------------------------------------
// Per 128x128 tile (upper triangle): bf16 mma.sync gram + masked KL epilogue.
// 8 warps in 4(M) x 2(N) grid, each 32x64; m16n8k16 fragments.
__global__ void __launch_bounds__(BDIM, 1)
pairs_kernel(int B, int H) {
    extern __shared__ char smem[];
    uint32_t sb = smem_u32(smem);
    const int tid  = threadIdx.x;
    const int wid  = tid >> 5;
    const int lane = tid & 31;
    const int wm   = wid >> 1;       // 0..3 (M)
    const int wn   = wid & 1;        // 0..1 (N)

    int nT = B / TILE;
    int I = 0, rem = blockIdx.x;
    while (rem >= nT - I) { rem -= nT - I; I++; }
    int J = I + rem;                 // I <= J

    // ---- stage pq tiles (128 x 16 bf16 each, 32B rows) + ne vectors -------
    {
        const __nv_bfloat16* pqI = g_pq + (size_t)(I * TILE) * 64;
        const __nv_bfloat16* pqJ = g_pq + (size_t)(J * TILE) * 64;
        for (int idx = tid; idx < 2048; idx += BDIM) {
            int side = idx >> 10;            // 0 = I, 1 = J
            int r2   = idx & 1023;
            int r    = r2 >> 3;
            int s    = r2 & 7;
            int sec = s >> 1, half = s & 1;  // sec: 0 lp_hi, 1 lp_lo, 2 q_hi, 3 q_lo
            const __nv_bfloat16* src = side ? pqJ : pqI;
            uint4 v = *(const uint4*)(src + (size_t)r * 64 + sec * 16 + half * 8);
            *(uint4*)(smem + PQ_OFF + (side * 4 + sec) * 4096 + r * 32 + half * 16) = v;
        }
        if (tid < TILE) {
            *(float*)(smem + NEI_OFF + tid * 4) = g_negent[I * TILE + tid];
            *(float*)(smem + NEJ_OFF + tid * 4) = g_negent[J * TILE + tid];
        }
    }

    const __nv_bfloat16* Agb = g_nembh + (size_t)(I * TILE) * H;
    const __nv_bfloat16* Bgb = g_nembh + (size_t)(J * TILE) * H;

    // A/B chunk: 128 rows x 16 16B-units, XOR swizzle u^(r&7)
    auto load_chunk = [&](int c, int buf) {
        uint32_t soff = sb + buf * 65536;
        const __nv_bfloat16* Ag = Agb + c * KC;
        const __nv_bfloat16* Bg = Bgb + c * KC;
        #pragma unroll
        for (int k = 0; k < 16; ++k) {
            int idx = tid + k * BDIM;            // 0..4095
            int t = idx >> 11;                   // 0 = A, 1 = B
            int r = (idx >> 4) & 127;
            int u = idx & 15;
            const __nv_bfloat16* g = (t ? Bg : Ag) + (size_t)r * H + u * 8;
            uint32_t sa = soff + t * 32768 + ((r * 16 + (u ^ (r & 7))) << 4);
            CP_ASYNC16(sa, g);
        }
    };

    float acc[2][8][4] = {};

    auto compute_chunk = [&](int buf) {
        uint32_t abase = sb + buf * 65536;
        uint32_t bbase = abase + 32768;
        int lrow = ((lane >> 3) & 1) * 8 + (lane & 7);   // row offset within 16
        int lu   = lane >> 4;                            // unit offset (0/1)
        #pragma unroll
        for (int s = 0; s < KC / 16; ++s) {
            uint32_t af[2][4];
            #pragma unroll
            for (int f = 0; f < 2; ++f) {
                int row = wm * 32 + f * 16 + lrow;
                int u = 2 * s + lu;
                ldsm4(af[f], abase + ((row * 16 + (u ^ (row & 7))) << 4));
            }
            uint32_t bfr[4][4];
            #pragma unroll
            for (int nb = 0; nb < 4; ++nb) {
                int row = wn * 64 + nb * 16 + lrow;
                int u = 2 * s + lu;
                ldsm4(bfr[nb], bbase + ((row * 16 + (u ^ (row & 7))) << 4));
            }
            #pragma unroll
            for (int f = 0; f < 2; ++f)
                #pragma unroll
                for (int nb = 0; nb < 4; ++nb) {
                    mma16816(acc[f][nb * 2 + 0], af[f], bfr[nb][0], bfr[nb][2]);
                    mma16816(acc[f][nb * 2 + 1], af[f], bfr[nb][1], bfr[nb][3]);
                }
        }
    };

    const int NCHUNK = H / KC;       // 8
    load_chunk(0, 0);
    CP_COMMIT();
    #pragma unroll 1
    for (int c = 0; c < NCHUNK; ++c) {
        if (c + 1 < NCHUNK) {
            load_chunk(c + 1, (c + 1) & 1);
            CP_COMMIT();
            CP_WAIT1();
        } else {
            CP_WAIT0();
        }
        __syncthreads();
        compute_chunk(c & 1);
        __syncthreads();
    }

    // ---- epilogue: mask from sim sign, ne sums, then mma KL dots ----------
    const float* neI = (const float*)(smem + NEI_OFF);
    const float* neJ = (const float*)(smem + NEJ_OFF);
    int g  = lane >> 2, tg = lane & 3;
    uint64_t mask = 0ull;
    int   cnt  = 0;
    float cons = 0.f;
    #pragma unroll
    for (int f = 0; f < 2; ++f) {
        int rl = wm * 32 + f * 16 + g;
        #pragma unroll
        for (int n8 = 0; n8 < 8; ++n8) {
            int c0 = wn * 64 + n8 * 8 + tg * 2;
            #pragma unroll
            for (int ci = 0; ci < 4; ++ci) {
                int rr = rl + (ci >> 1) * 8;
                int cc = c0 + (ci & 1);
                if (acc[f][n8][ci] > 0.f && (I != J || rr < cc)) {
                    mask |= 1ull << ((f * 8 + n8) * 4 + ci);
                    cnt  += 2;
                    cons += neI[rr] + neJ[cc];
                }
            }
        }
    }

    // K=16 mma pass over pq tiles (32B row stride, no swizzle)
    auto pq_pass = [&](int atile, int btile, float (*kl)[8][4]) {
        uint32_t ab = sb + PQ_OFF + atile * 4096;
        uint32_t bb = sb + PQ_OFF + btile * 4096;
        int lrow = ((lane >> 3) & 1) * 8 + (lane & 7);
        int lu16 = (lane >> 4) * 16;
        uint32_t af[2][4];
        #pragma unroll
        for (int f = 0; f < 2; ++f) {
            int row = wm * 32 + f * 16 + lrow;
            ldsm4(af[f], ab + row * 32 + lu16);
        }
        #pragma unroll
        for (int nb = 0; nb < 4; ++nb) {
            uint32_t b4[4];
            int row = wn * 64 + nb * 16 + lrow;
            ldsm4(b4, bb + row * 32 + lu16);
            #pragma unroll
            for (int f = 0; f < 2; ++f) {
                mma16816(kl[f][nb * 2 + 0], af[f], b4[0], b4[2]);
                mma16816(kl[f][nb * 2 + 1], af[f], b4[1], b4[3]);
            }
        }
    };

    {
        float kl[2][8][4] = {};
        pq_pass(0, 6, kl);   // lpI_hi . qJ_hi
        pq_pass(1, 6, kl);   // lpI_lo . qJ_hi
        pq_pass(0, 7, kl);   // lpI_hi . qJ_lo
        #pragma unroll
        for (int f = 0; f < 2; ++f)
            #pragma unroll
            for (int n8 = 0; n8 < 8; ++n8)
                #pragma unroll
                for (int ci = 0; ci < 4; ++ci) {
                    if ((mask >> ((f * 8 + n8) * 4 + ci)) & 1ull)
                        cons -= kl[f][n8][ci];
                    kl[f][n8][ci] = 0.f;
                }
        pq_pass(2, 4, kl);   // qI_hi . lpJ_hi
        pq_pass(3, 4, kl);   // qI_lo . lpJ_hi
        pq_pass(2, 5, kl);   // qI_hi . lpJ_lo
        #pragma unroll
        for (int f = 0; f < 2; ++f)
            #pragma unroll
            for (int n8 = 0; n8 < 8; ++n8)
                #pragma unroll
                for (int ci = 0; ci < 4; ++ci)
                    if ((mask >> ((f * 8 + n8) * 4 + ci)) & 1ull)
                        cons -= kl[f][n8][ci];
    }

    // ---- block reduce + atomics -------------------------------------------
    #pragma unroll
    for (int o = 16; o; o >>= 1) {
        cons += __shfl_xor_sync(0xffffffffu, cons, o);
        cnt  += __shfl_xor_sync(0xffffffffu, cnt, o);
    }
    __shared__ float wsum[8];
    __shared__ int   wcnt[8];
    if (lane == 0) { wsum[wid] = cons; wcnt[wid] = cnt; }
    __syncthreads();
    if (tid == 0) {
        float cs = 0.f; int cc = 0;
        #pragma unroll
        for (int w = 0; w < 8; w++) { cs += wsum[w]; cc += wcnt[w]; }
        atomicAdd(&g_cons, cs);
        atomicAdd(&g_pairs, (unsigned long long)cc);
    }
}

// ---------------------------------------------------------------------------
__global__ void finalize_kernel(float* __restrict__ out, int B) {
    if (threadIdx.x != 0) return;
    float invB = 1.f / (float)B;
    float u[NE], mean = 0.f;
    #pragma unroll
    for (int e = 0; e < NE; e++) { u[e] = g_usage[e] * invB; mean += u[e]; }
    mean /= (float)NE;
    float var = 0.f;
    #pragma unroll
    for (int e = 0; e < NE; e++) { float d = u[e] - mean; var += d * d; }
    var /= (float)(NE - 1);
    float load_balance = var * (float)(NE * NE);
    float entropy_loss = g_ent * invB;
    float efficiency   = g_eff * invB;
    unsigned long long np = g_pairs;
    float cons = (np > 0) ? (g_cons / (float)np) : 0.f;
    out[0] = load_balance + entropy_loss + efficiency + cons;
}

// ---------------------------------------------------------------------------
extern "C" void kernel_launch(void* const* d_in, const int* in_sizes, int n_in,
                              void* d_out, int out_size) {
    const float* rp  = (const float*)d_in[0];
    const float* emb = (const float*)d_in[1];
    float* out = (float*)d_out;
    int B = in_sizes[0] / NE;        // 4096
    int H = in_sizes[1] / B;         // 1024

    cudaFuncSetAttribute(pairs_kernel,
                         cudaFuncAttributeMaxDynamicSharedMemorySize, SMEM_BYTES);

    zero_kernel<<<1, 1>>>();
    prep_kernel<<<B / (BDIM / 32), BDIM>>>(rp, emb, B, H);
    int nT = B / TILE;
    int ntiles = nT * (nT + 1) / 2;  // 528
    pairs_kernel<<<ntiles, BDIM, SMEM_BYTES>>>(B, H);
    finalize_kernel<<<1, 32>>>(out, B);
}